// round 13
// baseline (speedup 1.0000x reference)
#include <cuda_runtime.h>

#define BB 64

__device__ float g_s0[2][BB * 10];
__device__ float g_s1[2][BB * 8192];
__device__ float g_s2[2][BB * 16384];
__device__ float g_p2[BB * 16384];
__device__ int   g_idx1[BB * 8192];
__device__ float g_c0scr[4 * BB * 128 * 256];
__device__ float g_upscr[4 * BB * 64 * 256];
__device__ float g_fcpart[BB * 8 * 10];

__device__ __forceinline__ float rho(float x) { return fminf(fmaxf(x, 0.f), 1.f); }

__device__ __forceinline__ void fma2(unsigned long long& a, unsigned long long x, unsigned long long y) {
    asm("fma.rn.f32x2 %0, %1, %2, %0;" : "+l"(a) : "l"(x), "l"(y));
}
__device__ __forceinline__ void upk(unsigned long long p, float& lo, float& hi) {
    asm("mov.b64 {%0, %1}, %2;" : "=f"(lo), "=f"(hi) : "l"(p));
}

// ============================================================================
// p2 = maxpool2x2(conv2d(data, conv1_w) + conv1_b)   (once)
// ============================================================================
__global__ void k_p2(const float* __restrict__ data, const float* __restrict__ w1,
                     const float* __restrict__ b1)
{
    int b = blockIdx.x, cg = blockIdx.y;
    __shared__ float sd[3][36][36];
    __shared__ float sw[16][75];
    int tid = threadIdx.x;
    for (int i = tid; i < 3 * 36 * 36; i += 256) {
        int c = i / 1296, r = i - c * 1296, yy = r / 36, xx = r - yy * 36;
        int y = yy - 2, x = xx - 2;
        float v = 0.f;
        if ((unsigned)y < 32u && (unsigned)x < 32u)
            v = data[((b * 3 + c) * 32 + y) * 32 + x];
        sd[c][yy][xx] = v;
    }
    for (int i = tid; i < 16 * 75; i += 256)
        sw[i / 75][i % 75] = w1[cg * 16 * 75 + i];
    __syncthreads();
    int wy = tid >> 4, wx = tid & 15;
    for (int c = 0; c < 16; c++) {
        float a00 = 0, a01 = 0, a10 = 0, a11 = 0;
        #pragma unroll
        for (int ci = 0; ci < 3; ci++)
            #pragma unroll
            for (int ky = 0; ky < 5; ky++)
                #pragma unroll
                for (int kx = 0; kx < 5; kx++) {
                    float wv = sw[c][ci * 25 + ky * 5 + kx];
                    a00 += sd[ci][2 * wy + ky][2 * wx + kx] * wv;
                    a01 += sd[ci][2 * wy + ky][2 * wx + kx + 1] * wv;
                    a10 += sd[ci][2 * wy + ky + 1][2 * wx + kx] * wv;
                    a11 += sd[ci][2 * wy + ky + 1][2 * wx + kx + 1] * wv;
                }
        float m = fmaxf(fmaxf(a00, a01), fmaxf(a10, a11)) + b1[cg * 16 + c];
        g_p2[((b * 64 + cg * 16 + c) * 16 + wy) * 16 + wx] = m;
    }
}

// ============================================================================
// K1a: conv0 split-K quarter. grid (64, 8, 4), 128 thr.
// Thread owns px (wy+8dy, wx+8dx); dup-float2 tile, pitch 24 -> conflict-free
// LDS.64 for both operands; inner unit = 8 LDS.64 + 16 FFMA2.
// ============================================================================
__global__ void __launch_bounds__(128) k_conv0_half(const float* __restrict__ s2o,
                                                    const float* __restrict__ w0)
{
    int b = blockIdx.x, cog = blockIdx.y, z = blockIdx.z;
    __shared__ float2 sin2[8][480];     // [ci][yy*24+xx], value duplicated
    __shared__ float sw[200][16];       // [ci*25+k][co]
    int tid = threadIdx.x;
    int w = tid & 63, ch = tid >> 6;
    int wy = w >> 3, wx = w & 7;
    unsigned long long acc2[2][2][4];
    #pragma unroll
    for (int q = 0; q < 16; q++) ((unsigned long long*)acc2)[q] = 0ull;

    #pragma unroll 1
    for (int ccl = 0; ccl < 2; ccl++) {
        int cc = z * 2 + ccl;
        for (int i = tid; i < 3200; i += 128) {
            int ci = i / 400, r = i - ci * 400, yy = r / 20, xx = r - yy * 20;
            int y = yy - 2, x = xx - 2;
            float v = 0.f;
            if ((unsigned)y < 16u && (unsigned)x < 16u)
                v = s2o[((b * 64 + cc * 8 + ci) * 16 + y) * 16 + x];
            sin2[ci][yy * 24 + xx] = make_float2(v, v);
        }
        for (int i = tid; i < 3200; i += 128) {
            int co = i & 15, r = i >> 4;
            sw[r][co] = w0[(cog * 16 + co) * 1600 + cc * 200 + r];
        }
        __syncthreads();
        #pragma unroll 2
        for (int ci = 0; ci < 8; ci++) {
            #pragma unroll
            for (int ky = 0; ky < 5; ky++) {
                #pragma unroll
                for (int kx = 0; kx < 5; kx++) {
                    int r = ci * 25 + ky * 5 + kx;
                    unsigned long long wv2[4];
                    #pragma unroll
                    for (int q = 0; q < 4; q++)
                        wv2[q] = *(const unsigned long long*)&sw[r][ch * 8 + 2 * q];
                    #pragma unroll
                    for (int dy = 0; dy < 2; dy++)
                        #pragma unroll
                        for (int dx = 0; dx < 2; dx++) {
                            unsigned long long iv2 = *(const unsigned long long*)
                                &sin2[ci][(wy + 8 * dy + ky) * 24 + wx + 8 * dx + kx];
                            #pragma unroll
                            for (int q = 0; q < 4; q++) fma2(acc2[dy][dx][q], iv2, wv2[q]);
                        }
                }
            }
        }
        __syncthreads();
    }

    #pragma unroll
    for (int q = 0; q < 4; q++) {
        int co = cog * 16 + ch * 8 + 2 * q;
        long base = ((long)(z * BB + b) * 128 + co) * 256;
        #pragma unroll
        for (int dy = 0; dy < 2; dy++)
            #pragma unroll
            for (int dx = 0; dx < 2; dx++) {
                float lo, hi;
                upk(acc2[dy][dx][q], lo, hi);
                int p = (wy + 8 * dy) * 16 + (wx + 8 * dx);
                g_c0scr[base + p] = lo;
                g_c0scr[base + 256 + p] = hi;
            }
    }
}

// ============================================================================
// K1b: sum 4 partials, maxpool+argmax, +b0, +topdown, rho
// ============================================================================
__global__ void k_pool_epi(const float* __restrict__ s0o, const float* __restrict__ b0,
                           const float* __restrict__ fcw, float* __restrict__ s1n)
{
    int idx = blockIdx.x * 256 + threadIdx.x;
    int b = idx >> 13, r = idx & 8191;
    int co = r >> 6, w = r & 63;
    int wy = w >> 3, wx = w & 7;
    const int ZS = BB * 128 * 256;
    int base = (b * 128 + co) * 256 + (2 * wy) * 16 + 2 * wx;
    float v0 = 0, v1 = 0, v2 = 0, v3 = 0;
    #pragma unroll
    for (int zz = 0; zz < 4; zz++) {
        v0 += g_c0scr[zz * ZS + base];
        v1 += g_c0scr[zz * ZS + base + 1];
        v2 += g_c0scr[zz * ZS + base + 16];
        v3 += g_c0scr[zz * ZS + base + 17];
    }
    float m = v0; int id = 0;
    if (v1 > m) { m = v1; id = 1; }
    if (v2 > m) { m = v2; id = 2; }
    if (v3 > m) { m = v3; id = 3; }
    m += b0[co];
    float td = 0.f;
    #pragma unroll
    for (int k = 0; k < 10; k++) td += s0o[b * 10 + k] * fcw[k * 8192 + r];
    s1n[idx] = rho(m + td);
    g_idx1[idx] = id;
}

// ============================================================================
// K2: fc split into 512 partial blocks + finisher
// ============================================================================
__global__ void k_fc_part(const float* __restrict__ s1o, const float* __restrict__ fcw)
{
    int b = blockIdx.x, seg = blockIdx.y;
    int tid = threadIdx.x;   // 128
    float part[10];
    #pragma unroll
    for (int j = 0; j < 10; j++) part[j] = 0.f;
    int base = seg * 1024;
    for (int k = base + tid; k < base + 1024; k += 128) {
        float v = s1o[b * 8192 + k];
        #pragma unroll
        for (int j = 0; j < 10; j++) part[j] += v * fcw[j * 8192 + k];
    }
    __shared__ float red[10][128];
    #pragma unroll
    for (int j = 0; j < 10; j++) red[j][tid] = part[j];
    __syncthreads();
    for (int s = 64; s > 0; s >>= 1) {
        if (tid < s) {
            #pragma unroll
            for (int j = 0; j < 10; j++) red[j][tid] += red[j][tid + s];
        }
        __syncthreads();
    }
    if (tid < 10) g_fcpart[(b * 8 + seg) * 10 + tid] = red[tid][0];
}
__global__ void k_fc_fin(const float* __restrict__ fcb, float* __restrict__ s0n)
{
    int b = blockIdx.x, j = threadIdx.x;   // <<<64, 32>>>
    if (j < 10) {
        float s = 0.f;
        #pragma unroll
        for (int q = 0; q < 8; q++) s += g_fcpart[(b * 8 + q) * 10 + j];
        s0n[b * 10 + j] = rho(s + fcb[j]);
    }
}

// ============================================================================
// K3a: upconv split-K quarter. grid (64, 4, 4), 128 thr. Same inner scheme.
// ============================================================================
__global__ void __launch_bounds__(128) k_upconv_half(const float* __restrict__ s1o,
                                                     const float* __restrict__ w0)
{
    int b = blockIdx.x, og = blockIdx.y, z = blockIdx.z;
    __shared__ float2 su2[8][480];
    __shared__ float sw[200][16];       // [ci*25+k][o]
    int tid = threadIdx.x;
    int w = tid & 63, oh = tid >> 6;
    int wy = w >> 3, wx = w & 7;
    unsigned long long acc2[2][2][4];
    #pragma unroll
    for (int q = 0; q < 16; q++) ((unsigned long long*)acc2)[q] = 0ull;

    #pragma unroll 1
    for (int ccl = 0; ccl < 4; ccl++) {
        int cc = z * 4 + ccl;
        for (int i = tid; i < 3200; i += 128) {
            int ci = i / 400, r = i - ci * 400, yy = r / 20, xx = r - yy * 20;
            int y = yy - 2, x = xx - 2;
            float v = 0.f;
            if ((unsigned)y < 16u && (unsigned)x < 16u) {
                int co = cc * 8 + ci;
                int sb = b * 8192 + co * 64 + (y >> 1) * 8 + (x >> 1);
                int pos = ((y & 1) << 1) | (x & 1);
                v = (g_idx1[sb] == pos) ? s1o[sb] : 0.f;
            }
            su2[ci][yy * 24 + xx] = make_float2(v, v);
        }
        for (int i = tid; i < 3200; i += 128) {
            int o = i & 15, r = i >> 4;
            int ci = r / 25, k = r - ci * 25;
            sw[r][o] = w0[(cc * 8 + ci) * 1600 + (og * 16 + o) * 25 + (24 - k)];
        }
        __syncthreads();
        #pragma unroll 2
        for (int ci = 0; ci < 8; ci++) {
            #pragma unroll
            for (int ky = 0; ky < 5; ky++) {
                #pragma unroll
                for (int kx = 0; kx < 5; kx++) {
                    int r = ci * 25 + ky * 5 + kx;
                    unsigned long long wv2[4];
                    #pragma unroll
                    for (int q = 0; q < 4; q++)
                        wv2[q] = *(const unsigned long long*)&sw[r][oh * 8 + 2 * q];
                    #pragma unroll
                    for (int dy = 0; dy < 2; dy++)
                        #pragma unroll
                        for (int dx = 0; dx < 2; dx++) {
                            unsigned long long iv2 = *(const unsigned long long*)
                                &su2[ci][(wy + 8 * dy + ky) * 24 + wx + 8 * dx + kx];
                            #pragma unroll
                            for (int q = 0; q < 4; q++) fma2(acc2[dy][dx][q], iv2, wv2[q]);
                        }
                }
            }
        }
        __syncthreads();
    }

    #pragma unroll
    for (int q = 0; q < 4; q++) {
        int o = og * 16 + oh * 8 + 2 * q;
        long base = ((long)(z * BB + b) * 64 + o) * 256;
        #pragma unroll
        for (int dy = 0; dy < 2; dy++)
            #pragma unroll
            for (int dx = 0; dx < 2; dx++) {
                float lo, hi;
                upk(acc2[dy][dx][q], lo, hi);
                int p = (wy + 8 * dy) * 16 + (wx + 8 * dx);
                g_upscr[base + p] = lo;
                g_upscr[base + 256 + p] = hi;
            }
    }
}

// ============================================================================
// K3b: s2_new = rho(p2 + sum of 4 partials)
// ============================================================================
__global__ void k_s2_epi(float* __restrict__ s2n)
{
    const int ZS = BB * 64 * 256;
    int i = blockIdx.x * 256 + threadIdx.x;
    s2n[i] = rho(g_p2[i] + ((g_upscr[i] + g_upscr[ZS + i]) +
                            (g_upscr[2 * ZS + i] + g_upscr[3 * ZS + i])));
}

// ============================================================================
extern "C" void kernel_launch(void* const* d_in, const int* in_sizes, int n_in,
                              void* d_out, int out_size)
{
    const float* data = (const float*)d_in[0];
    const float* s0i  = (const float*)d_in[1];
    const float* s1i  = (const float*)d_in[2];
    const float* s2i  = (const float*)d_in[3];
    const float* w0   = (const float*)d_in[4];
    const float* b0   = (const float*)d_in[5];
    const float* w1   = (const float*)d_in[6];
    const float* b1   = (const float*)d_in[7];
    const float* fcw  = (const float*)d_in[8];
    const float* fcb  = (const float*)d_in[9];
    float* out = (float*)d_out;

    float *ps0, *ps1, *ps2;
    cudaGetSymbolAddress((void**)&ps0, g_s0);
    cudaGetSymbolAddress((void**)&ps1, g_s1);
    cudaGetSymbolAddress((void**)&ps2, g_s2);

    k_p2<<<dim3(64, 4), 256>>>(data, w1, b1);

    const float *cs0 = s0i, *cs1 = s1i, *cs2 = s2i;
    for (int t = 0; t < 10; t++) {
        int nb = t & 1;
        float* ns0 = ps0 + nb * (BB * 10);
        float* ns1 = ps1 + nb * (BB * 8192);
        float* ns2 = ps2 + nb * (BB * 16384);
        k_conv0_half<<<dim3(64, 8, 4), 128>>>(cs2, w0);
        k_pool_epi<<<2048, 256>>>(cs0, b0, fcw, ns1);
        k_fc_part<<<dim3(64, 8), 128>>>(cs1, fcw);
        k_fc_fin<<<64, 32>>>(fcb, ns0);
        k_upconv_half<<<dim3(64, 4, 4), 128>>>(cs1, w0);
        k_s2_epi<<<4096, 256>>>(ns2);
        cs0 = ns0; cs1 = ns1; cs2 = ns2;
        if (t == 6) {
            cudaMemcpyAsync(out + 1573504, cs0, 640 * sizeof(float),     cudaMemcpyDeviceToDevice, 0);
            cudaMemcpyAsync(out + 1574144, cs1, 524288 * sizeof(float),  cudaMemcpyDeviceToDevice, 0);
            cudaMemcpyAsync(out + 2098432, cs2, 1048576 * sizeof(float), cudaMemcpyDeviceToDevice, 0);
        }
    }
    cudaMemcpyAsync(out,          cs0, 640 * sizeof(float),     cudaMemcpyDeviceToDevice, 0);
    cudaMemcpyAsync(out + 640,    cs1, 524288 * sizeof(float),  cudaMemcpyDeviceToDevice, 0);
    cudaMemcpyAsync(out + 524928, cs2, 1048576 * sizeof(float), cudaMemcpyDeviceToDevice, 0);
}

// round 14
// speedup vs baseline: 1.1851x; 1.1851x over previous
#include <cuda_runtime.h>

#define BB 64

__device__ float g_s0[2][BB * 10];
__device__ float g_s1[2][BB * 8192];
__device__ float g_s2[2][BB * 16384];
__device__ float g_p2[BB * 16384];
__device__ int   g_idx1[BB * 8192];
__device__ float g_c0scr[4 * BB * 128 * 256];
__device__ float g_upscr[8 * BB * 64 * 256];
__device__ float g_fcpart[BB * 8 * 10];

__device__ __forceinline__ float rho(float x) { return fminf(fmaxf(x, 0.f), 1.f); }

__device__ __forceinline__ void fma2(unsigned long long& a, unsigned long long x, unsigned long long y) {
    asm("fma.rn.f32x2 %0, %1, %2, %0;" : "+l"(a) : "l"(x), "l"(y));
}
__device__ __forceinline__ unsigned long long pk2(float v) {
    unsigned long long r; asm("mov.b64 %0, {%1, %1};" : "=l"(r) : "f"(v)); return r;
}
__device__ __forceinline__ void upk(unsigned long long p, float& lo, float& hi) {
    asm("mov.b64 {%0, %1}, %2;" : "=f"(lo), "=f"(hi) : "l"(p));
}

// ============================================================================
// p2 = maxpool2x2(conv2d(data, conv1_w) + conv1_b)   (once)
// ============================================================================
__global__ void k_p2(const float* __restrict__ data, const float* __restrict__ w1,
                     const float* __restrict__ b1)
{
    int b = blockIdx.x, cg = blockIdx.y;
    __shared__ float sd[3][36][36];
    __shared__ float sw[16][75];
    int tid = threadIdx.x;
    for (int i = tid; i < 3 * 36 * 36; i += 256) {
        int c = i / 1296, r = i - c * 1296, yy = r / 36, xx = r - yy * 36;
        int y = yy - 2, x = xx - 2;
        float v = 0.f;
        if ((unsigned)y < 32u && (unsigned)x < 32u)
            v = data[((b * 3 + c) * 32 + y) * 32 + x];
        sd[c][yy][xx] = v;
    }
    for (int i = tid; i < 16 * 75; i += 256)
        sw[i / 75][i % 75] = w1[cg * 16 * 75 + i];
    __syncthreads();
    int wy = tid >> 4, wx = tid & 15;
    for (int c = 0; c < 16; c++) {
        float a00 = 0, a01 = 0, a10 = 0, a11 = 0;
        #pragma unroll
        for (int ci = 0; ci < 3; ci++)
            #pragma unroll
            for (int ky = 0; ky < 5; ky++)
                #pragma unroll
                for (int kx = 0; kx < 5; kx++) {
                    float wv = sw[c][ci * 25 + ky * 5 + kx];
                    a00 += sd[ci][2 * wy + ky][2 * wx + kx] * wv;
                    a01 += sd[ci][2 * wy + ky][2 * wx + kx + 1] * wv;
                    a10 += sd[ci][2 * wy + ky + 1][2 * wx + kx] * wv;
                    a11 += sd[ci][2 * wy + ky + 1][2 * wx + kx + 1] * wv;
                }
        float m = fmaxf(fmaxf(a00, a01), fmaxf(a10, a11)) + b1[cg * 16 + c];
        g_p2[((b * 64 + cg * 16 + c) * 16 + wy) * 16 + wx] = m;
    }
}

// ============================================================================
// K1a: conv0 split-K quarter (2 ci-chunks of 8) -> pre-pool partials
// grid (64, 8, 4), 128 threads. f32x2 packed math.   [exact R4 kernel]
// ============================================================================
__global__ void k_conv0_half(const float* __restrict__ s2o, const float* __restrict__ w0)
{
    int b = blockIdx.x, cog = blockIdx.y, z = blockIdx.z;
    __shared__ float sin_[8][20][20];
    __shared__ float sw[200][16];       // [ci*25+k][co]
    int tid = threadIdx.x;
    int w = tid & 63, ch = tid >> 6;
    int wy = w >> 3, wx = w & 7;
    unsigned long long acc2[2][2][4];
    #pragma unroll
    for (int q = 0; q < 16; q++) ((unsigned long long*)acc2)[q] = 0ull;

    #pragma unroll 1
    for (int ccl = 0; ccl < 2; ccl++) {
        int cc = z * 2 + ccl;
        for (int i = tid; i < 3200; i += 128) {
            int ci = i / 400, r = i - ci * 400, yy = r / 20, xx = r - yy * 20;
            int y = yy - 2, x = xx - 2;
            float v = 0.f;
            if ((unsigned)y < 16u && (unsigned)x < 16u)
                v = s2o[((b * 64 + cc * 8 + ci) * 16 + y) * 16 + x];
            sin_[ci][yy][xx] = v;
        }
        for (int i = tid; i < 3200; i += 128) {
            int co = i & 15, r = i >> 4;
            sw[r][co] = w0[(cog * 16 + co) * 1600 + cc * 200 + r];
        }
        __syncthreads();
        #pragma unroll 1
        for (int ci = 0; ci < 8; ci++) {
            #pragma unroll
            for (int ky = 0; ky < 5; ky++) {
                #pragma unroll
                for (int kx = 0; kx < 5; kx++) {
                    int r = ci * 25 + ky * 5 + kx;
                    unsigned long long wv2[4];
                    #pragma unroll
                    for (int q = 0; q < 4; q++)
                        wv2[q] = *(const unsigned long long*)&sw[r][ch * 8 + 2 * q];
                    #pragma unroll
                    for (int dy = 0; dy < 2; dy++)
                        #pragma unroll
                        for (int dx = 0; dx < 2; dx++) {
                            unsigned long long iv2 = pk2(sin_[ci][2 * wy + dy + ky][2 * wx + dx + kx]);
                            #pragma unroll
                            for (int q = 0; q < 4; q++) fma2(acc2[dy][dx][q], iv2, wv2[q]);
                        }
                }
            }
        }
        __syncthreads();
    }

    #pragma unroll
    for (int q = 0; q < 4; q++) {
        int co = cog * 16 + ch * 8 + 2 * q;
        long base = ((long)(z * BB + b) * 128 + co) * 256;
        #pragma unroll
        for (int dy = 0; dy < 2; dy++)
            #pragma unroll
            for (int dx = 0; dx < 2; dx++) {
                float lo, hi;
                upk(acc2[dy][dx][q], lo, hi);
                int p = (2 * wy + dy) * 16 + (2 * wx + dx);
                g_c0scr[base + p] = lo;
                g_c0scr[base + 256 + p] = hi;
            }
    }
}

// ============================================================================
// K1b: sum 4 partials, maxpool+argmax, +b0, +topdown, rho
// ============================================================================
__global__ void k_pool_epi(const float* __restrict__ s0o, const float* __restrict__ b0,
                           const float* __restrict__ fcw, float* __restrict__ s1n)
{
    int idx = blockIdx.x * 256 + threadIdx.x;
    int b = idx >> 13, r = idx & 8191;
    int co = r >> 6, w = r & 63;
    int wy = w >> 3, wx = w & 7;
    const int ZS = BB * 128 * 256;
    int base = (b * 128 + co) * 256 + (2 * wy) * 16 + 2 * wx;
    float v0 = 0, v1 = 0, v2 = 0, v3 = 0;
    #pragma unroll
    for (int zz = 0; zz < 4; zz++) {
        v0 += g_c0scr[zz * ZS + base];
        v1 += g_c0scr[zz * ZS + base + 1];
        v2 += g_c0scr[zz * ZS + base + 16];
        v3 += g_c0scr[zz * ZS + base + 17];
    }
    float m = v0; int id = 0;
    if (v1 > m) { m = v1; id = 1; }
    if (v2 > m) { m = v2; id = 2; }
    if (v3 > m) { m = v3; id = 3; }
    m += b0[co];
    float td = 0.f;
    #pragma unroll
    for (int k = 0; k < 10; k++) td += s0o[b * 10 + k] * fcw[k * 8192 + r];
    s1n[idx] = rho(m + td);
    g_idx1[idx] = id;
}

// ============================================================================
// K2: fc split into 512 partial blocks + finisher
// ============================================================================
__global__ void k_fc_part(const float* __restrict__ s1o, const float* __restrict__ fcw)
{
    int b = blockIdx.x, seg = blockIdx.y;
    int tid = threadIdx.x;   // 128
    float part[10];
    #pragma unroll
    for (int j = 0; j < 10; j++) part[j] = 0.f;
    int base = seg * 1024;
    for (int k = base + tid; k < base + 1024; k += 128) {
        float v = s1o[b * 8192 + k];
        #pragma unroll
        for (int j = 0; j < 10; j++) part[j] += v * fcw[j * 8192 + k];
    }
    __shared__ float red[10][128];
    #pragma unroll
    for (int j = 0; j < 10; j++) red[j][tid] = part[j];
    __syncthreads();
    for (int s = 64; s > 0; s >>= 1) {
        if (tid < s) {
            #pragma unroll
            for (int j = 0; j < 10; j++) red[j][tid] += red[j][tid + s];
        }
        __syncthreads();
    }
    if (tid < 10) g_fcpart[(b * 8 + seg) * 10 + tid] = red[tid][0];
}
__global__ void k_fc_fin(const float* __restrict__ fcb, float* __restrict__ s0n)
{
    int b = blockIdx.x, j = threadIdx.x;   // <<<64, 32>>>
    if (j < 10) {
        float s = 0.f;
        #pragma unroll
        for (int q = 0; q < 8; q++) s += g_fcpart[(b * 8 + q) * 10 + j];
        s0n[b * 10 + j] = rho(s + fcb[j]);
    }
}

// ============================================================================
// K3a: upconv split-K eighth (2 ci-chunks of 8) -> partials
// grid (64, 4, 8), 128 threads. f32x2 packed math. [R4 kernel, deeper split]
// ============================================================================
__global__ void k_upconv_half(const float* __restrict__ s1o, const float* __restrict__ w0)
{
    int b = blockIdx.x, og = blockIdx.y, z = blockIdx.z;
    __shared__ float su[8][20][20];
    __shared__ float sw[200][16];       // [ci*25+k][o]
    int tid = threadIdx.x;
    int w = tid & 63, oh = tid >> 6;
    int wy = w >> 3, wx = w & 7;
    unsigned long long acc2[2][2][4];
    #pragma unroll
    for (int q = 0; q < 16; q++) ((unsigned long long*)acc2)[q] = 0ull;

    #pragma unroll 1
    for (int ccl = 0; ccl < 2; ccl++) {
        int cc = z * 2 + ccl;
        for (int i = tid; i < 3200; i += 128) {
            int ci = i / 400, r = i - ci * 400, yy = r / 20, xx = r - yy * 20;
            int y = yy - 2, x = xx - 2;
            float v = 0.f;
            if ((unsigned)y < 16u && (unsigned)x < 16u) {
                int co = cc * 8 + ci;
                int base = b * 8192 + co * 64 + (y >> 1) * 8 + (x >> 1);
                int pos = ((y & 1) << 1) | (x & 1);
                v = (g_idx1[base] == pos) ? s1o[base] : 0.f;
            }
            su[ci][yy][xx] = v;
        }
        for (int i = tid; i < 3200; i += 128) {
            int o = i & 15, r = i >> 4;
            int ci = r / 25, k = r - ci * 25;
            sw[r][o] = w0[(cc * 8 + ci) * 1600 + (og * 16 + o) * 25 + (24 - k)];
        }
        __syncthreads();
        #pragma unroll 1
        for (int ci = 0; ci < 8; ci++) {
            #pragma unroll
            for (int ky = 0; ky < 5; ky++) {
                #pragma unroll
                for (int kx = 0; kx < 5; kx++) {
                    int r = ci * 25 + ky * 5 + kx;
                    unsigned long long wv2[4];
                    #pragma unroll
                    for (int q = 0; q < 4; q++)
                        wv2[q] = *(const unsigned long long*)&sw[r][oh * 8 + 2 * q];
                    #pragma unroll
                    for (int dy = 0; dy < 2; dy++)
                        #pragma unroll
                        for (int dx = 0; dx < 2; dx++) {
                            unsigned long long iv2 = pk2(su[ci][2 * wy + dy + ky][2 * wx + dx + kx]);
                            #pragma unroll
                            for (int q = 0; q < 4; q++) fma2(acc2[dy][dx][q], iv2, wv2[q]);
                        }
                }
            }
        }
        __syncthreads();
    }

    #pragma unroll
    for (int q = 0; q < 4; q++) {
        int o = og * 16 + oh * 8 + 2 * q;
        long base = ((long)(z * BB + b) * 64 + o) * 256;
        #pragma unroll
        for (int dy = 0; dy < 2; dy++)
            #pragma unroll
            for (int dx = 0; dx < 2; dx++) {
                float lo, hi;
                upk(acc2[dy][dx][q], lo, hi);
                int p = (2 * wy + dy) * 16 + (2 * wx + dx);
                g_upscr[base + p] = lo;
                g_upscr[base + 256 + p] = hi;
            }
    }
}

// ============================================================================
// K3b: s2_new = rho(p2 + sum of 8 partials)
// ============================================================================
__global__ void k_s2_epi(float* __restrict__ s2n)
{
    const int ZS = BB * 64 * 256;
    int i = blockIdx.x * 256 + threadIdx.x;
    float s01 = g_upscr[i] + g_upscr[ZS + i];
    float s23 = g_upscr[2 * ZS + i] + g_upscr[3 * ZS + i];
    float s45 = g_upscr[4 * ZS + i] + g_upscr[5 * ZS + i];
    float s67 = g_upscr[6 * ZS + i] + g_upscr[7 * ZS + i];
    s2n[i] = rho(g_p2[i] + ((s01 + s23) + (s45 + s67)));
}

// ============================================================================
extern "C" void kernel_launch(void* const* d_in, const int* in_sizes, int n_in,
                              void* d_out, int out_size)
{
    const float* data = (const float*)d_in[0];
    const float* s0i  = (const float*)d_in[1];
    const float* s1i  = (const float*)d_in[2];
    const float* s2i  = (const float*)d_in[3];
    const float* w0   = (const float*)d_in[4];
    const float* b0   = (const float*)d_in[5];
    const float* w1   = (const float*)d_in[6];
    const float* b1   = (const float*)d_in[7];
    const float* fcw  = (const float*)d_in[8];
    const float* fcb  = (const float*)d_in[9];
    float* out = (float*)d_out;

    float *ps0, *ps1, *ps2;
    cudaGetSymbolAddress((void**)&ps0, g_s0);
    cudaGetSymbolAddress((void**)&ps1, g_s1);
    cudaGetSymbolAddress((void**)&ps2, g_s2);

    k_p2<<<dim3(64, 4), 256>>>(data, w1, b1);

    const float *cs0 = s0i, *cs1 = s1i, *cs2 = s2i;
    for (int t = 0; t < 10; t++) {
        int nb = t & 1;
        float* ns0 = ps0 + nb * (BB * 10);
        float* ns1 = ps1 + nb * (BB * 8192);
        float* ns2 = ps2 + nb * (BB * 16384);
        k_conv0_half<<<dim3(64, 8, 4), 128>>>(cs2, w0);
        k_pool_epi<<<2048, 256>>>(cs0, b0, fcw, ns1);
        k_fc_part<<<dim3(64, 8), 128>>>(cs1, fcw);
        k_fc_fin<<<64, 32>>>(fcb, ns0);
        k_upconv_half<<<dim3(64, 4, 8), 128>>>(cs1, w0);
        k_s2_epi<<<4096, 256>>>(ns2);
        cs0 = ns0; cs1 = ns1; cs2 = ns2;
        if (t == 6) {
            cudaMemcpyAsync(out + 1573504, cs0, 640 * sizeof(float),     cudaMemcpyDeviceToDevice, 0);
            cudaMemcpyAsync(out + 1574144, cs1, 524288 * sizeof(float),  cudaMemcpyDeviceToDevice, 0);
            cudaMemcpyAsync(out + 2098432, cs2, 1048576 * sizeof(float), cudaMemcpyDeviceToDevice, 0);
        }
    }
    cudaMemcpyAsync(out,          cs0, 640 * sizeof(float),     cudaMemcpyDeviceToDevice, 0);
    cudaMemcpyAsync(out + 640,    cs1, 524288 * sizeof(float),  cudaMemcpyDeviceToDevice, 0);
    cudaMemcpyAsync(out + 524928, cs2, 1048576 * sizeof(float), cudaMemcpyDeviceToDevice, 0);
}

// round 15
// speedup vs baseline: 1.2009x; 1.0133x over previous
#include <cuda_runtime.h>

#define BB 64

__device__ float g_s0[2][BB * 10];
__device__ float g_s1[2][BB * 8192];
__device__ float g_s2[2][BB * 16384];
__device__ float g_p2[BB * 16384];
__device__ int   g_idx1[BB * 8192];
__device__ float g_c0scr[4 * BB * 128 * 256];
__device__ float g_upscr[8 * BB * 64 * 256];
__device__ float g_fcpart[BB * 8 * 10];

__device__ __forceinline__ float rho(float x) { return fminf(fmaxf(x, 0.f), 1.f); }

__device__ __forceinline__ void fma2(unsigned long long& a, unsigned long long x, unsigned long long y) {
    asm("fma.rn.f32x2 %0, %1, %2, %0;" : "+l"(a) : "l"(x), "l"(y));
}
__device__ __forceinline__ unsigned long long pk2(float v) {
    unsigned long long r; asm("mov.b64 %0, {%1, %1};" : "=l"(r) : "f"(v)); return r;
}
__device__ __forceinline__ void upk(unsigned long long p, float& lo, float& hi) {
    asm("mov.b64 {%0, %1}, %2;" : "=f"(lo), "=f"(hi) : "l"(p));
}

// ============================================================================
// p2 = maxpool2x2(conv2d(data, conv1_w) + conv1_b)   (once)
// ============================================================================
__global__ void k_p2(const float* __restrict__ data, const float* __restrict__ w1,
                     const float* __restrict__ b1)
{
    int b = blockIdx.x, cg = blockIdx.y;
    __shared__ float sd[3][36][36];
    __shared__ float sw[16][75];
    int tid = threadIdx.x;
    for (int i = tid; i < 3 * 36 * 36; i += 256) {
        int c = i / 1296, r = i - c * 1296, yy = r / 36, xx = r - yy * 36;
        int y = yy - 2, x = xx - 2;
        float v = 0.f;
        if ((unsigned)y < 32u && (unsigned)x < 32u)
            v = data[((b * 3 + c) * 32 + y) * 32 + x];
        sd[c][yy][xx] = v;
    }
    for (int i = tid; i < 16 * 75; i += 256)
        sw[i / 75][i % 75] = w1[cg * 16 * 75 + i];
    __syncthreads();
    int wy = tid >> 4, wx = tid & 15;
    for (int c = 0; c < 16; c++) {
        float a00 = 0, a01 = 0, a10 = 0, a11 = 0;
        #pragma unroll
        for (int ci = 0; ci < 3; ci++)
            #pragma unroll
            for (int ky = 0; ky < 5; ky++)
                #pragma unroll
                for (int kx = 0; kx < 5; kx++) {
                    float wv = sw[c][ci * 25 + ky * 5 + kx];
                    a00 += sd[ci][2 * wy + ky][2 * wx + kx] * wv;
                    a01 += sd[ci][2 * wy + ky][2 * wx + kx + 1] * wv;
                    a10 += sd[ci][2 * wy + ky + 1][2 * wx + kx] * wv;
                    a11 += sd[ci][2 * wy + ky + 1][2 * wx + kx + 1] * wv;
                }
        float m = fmaxf(fmaxf(a00, a01), fmaxf(a10, a11)) + b1[cg * 16 + c];
        g_p2[((b * 64 + cg * 16 + c) * 16 + wy) * 16 + wx] = m;
    }
}

// ============================================================================
// K1a: conv0 split-K quarter (2 ci-chunks of 8) -> pre-pool partials
// grid (64, 8, 4), 128 threads. f32x2 packed math.
// ============================================================================
__global__ void k_conv0_half(const float* __restrict__ s2o, const float* __restrict__ w0)
{
    int b = blockIdx.x, cog = blockIdx.y, z = blockIdx.z;
    __shared__ float sin_[8][20][20];
    __shared__ float sw[200][16];       // [ci*25+k][co]
    int tid = threadIdx.x;
    int w = tid & 63, ch = tid >> 6;
    int wy = w >> 3, wx = w & 7;
    unsigned long long acc2[2][2][4];
    #pragma unroll
    for (int q = 0; q < 16; q++) ((unsigned long long*)acc2)[q] = 0ull;

    #pragma unroll 1
    for (int ccl = 0; ccl < 2; ccl++) {
        int cc = z * 2 + ccl;
        for (int i = tid; i < 3200; i += 128) {
            int ci = i / 400, r = i - ci * 400, yy = r / 20, xx = r - yy * 20;
            int y = yy - 2, x = xx - 2;
            float v = 0.f;
            if ((unsigned)y < 16u && (unsigned)x < 16u)
                v = s2o[((b * 64 + cc * 8 + ci) * 16 + y) * 16 + x];
            sin_[ci][yy][xx] = v;
        }
        for (int i = tid; i < 3200; i += 128) {
            int co = i & 15, r = i >> 4;
            sw[r][co] = w0[(cog * 16 + co) * 1600 + cc * 200 + r];
        }
        __syncthreads();
        #pragma unroll 1
        for (int ci = 0; ci < 8; ci++) {
            #pragma unroll
            for (int ky = 0; ky < 5; ky++) {
                #pragma unroll
                for (int kx = 0; kx < 5; kx++) {
                    int r = ci * 25 + ky * 5 + kx;
                    unsigned long long wv2[4];
                    #pragma unroll
                    for (int q = 0; q < 4; q++)
                        wv2[q] = *(const unsigned long long*)&sw[r][ch * 8 + 2 * q];
                    #pragma unroll
                    for (int dy = 0; dy < 2; dy++)
                        #pragma unroll
                        for (int dx = 0; dx < 2; dx++) {
                            unsigned long long iv2 = pk2(sin_[ci][2 * wy + dy + ky][2 * wx + dx + kx]);
                            #pragma unroll
                            for (int q = 0; q < 4; q++) fma2(acc2[dy][dx][q], iv2, wv2[q]);
                        }
                }
            }
        }
        __syncthreads();
    }

    #pragma unroll
    for (int q = 0; q < 4; q++) {
        int co = cog * 16 + ch * 8 + 2 * q;
        long base = ((long)(z * BB + b) * 128 + co) * 256;
        #pragma unroll
        for (int dy = 0; dy < 2; dy++)
            #pragma unroll
            for (int dx = 0; dx < 2; dx++) {
                float lo, hi;
                upk(acc2[dy][dx][q], lo, hi);
                int p = (2 * wy + dy) * 16 + (2 * wx + dx);
                g_c0scr[base + p] = lo;
                g_c0scr[base + 256 + p] = hi;
            }
    }
}

// ============================================================================
// K1b: sum 4 partials, maxpool+argmax, +b0, +topdown, rho
// ============================================================================
__global__ void k_pool_epi(const float* __restrict__ s0o, const float* __restrict__ b0,
                           const float* __restrict__ fcw, float* __restrict__ s1n)
{
    int idx = blockIdx.x * 256 + threadIdx.x;
    int b = idx >> 13, r = idx & 8191;
    int co = r >> 6, w = r & 63;
    int wy = w >> 3, wx = w & 7;
    const int ZS = BB * 128 * 256;
    int base = (b * 128 + co) * 256 + (2 * wy) * 16 + 2 * wx;
    float v0 = 0, v1 = 0, v2 = 0, v3 = 0;
    #pragma unroll
    for (int zz = 0; zz < 4; zz++) {
        v0 += g_c0scr[zz * ZS + base];
        v1 += g_c0scr[zz * ZS + base + 1];
        v2 += g_c0scr[zz * ZS + base + 16];
        v3 += g_c0scr[zz * ZS + base + 17];
    }
    float m = v0; int id = 0;
    if (v1 > m) { m = v1; id = 1; }
    if (v2 > m) { m = v2; id = 2; }
    if (v3 > m) { m = v3; id = 3; }
    m += b0[co];
    float td = 0.f;
    #pragma unroll
    for (int k = 0; k < 10; k++) td += s0o[b * 10 + k] * fcw[k * 8192 + r];
    s1n[idx] = rho(m + td);
    g_idx1[idx] = id;
}

// ============================================================================
// K2: fc split into 512 partial blocks + finisher  (side stream)
// ============================================================================
__global__ void k_fc_part(const float* __restrict__ s1o, const float* __restrict__ fcw)
{
    int b = blockIdx.x, seg = blockIdx.y;
    int tid = threadIdx.x;   // 128
    float part[10];
    #pragma unroll
    for (int j = 0; j < 10; j++) part[j] = 0.f;
    int base = seg * 1024;
    for (int k = base + tid; k < base + 1024; k += 128) {
        float v = s1o[b * 8192 + k];
        #pragma unroll
        for (int j = 0; j < 10; j++) part[j] += v * fcw[j * 8192 + k];
    }
    __shared__ float red[10][128];
    #pragma unroll
    for (int j = 0; j < 10; j++) red[j][tid] = part[j];
    __syncthreads();
    for (int s = 64; s > 0; s >>= 1) {
        if (tid < s) {
            #pragma unroll
            for (int j = 0; j < 10; j++) red[j][tid] += red[j][tid + s];
        }
        __syncthreads();
    }
    if (tid < 10) g_fcpart[(b * 8 + seg) * 10 + tid] = red[tid][0];
}
__global__ void k_fc_fin(const float* __restrict__ fcb, float* __restrict__ s0n)
{
    int b = blockIdx.x, j = threadIdx.x;   // <<<64, 32>>>
    if (j < 10) {
        float s = 0.f;
        #pragma unroll
        for (int q = 0; q < 8; q++) s += g_fcpart[(b * 8 + q) * 10 + j];
        s0n[b * 10 + j] = rho(s + fcb[j]);
    }
}

// ============================================================================
// K3a: upconv split-K eighth (2 ci-chunks of 8) -> partials
// grid (64, 4, 8), 128 threads. f32x2 packed math.
// ============================================================================
__global__ void k_upconv_half(const float* __restrict__ s1o, const float* __restrict__ w0)
{
    int b = blockIdx.x, og = blockIdx.y, z = blockIdx.z;
    __shared__ float su[8][20][20];
    __shared__ float sw[200][16];       // [ci*25+k][o]
    int tid = threadIdx.x;
    int w = tid & 63, oh = tid >> 6;
    int wy = w >> 3, wx = w & 7;
    unsigned long long acc2[2][2][4];
    #pragma unroll
    for (int q = 0; q < 16; q++) ((unsigned long long*)acc2)[q] = 0ull;

    #pragma unroll 1
    for (int ccl = 0; ccl < 2; ccl++) {
        int cc = z * 2 + ccl;
        for (int i = tid; i < 3200; i += 128) {
            int ci = i / 400, r = i - ci * 400, yy = r / 20, xx = r - yy * 20;
            int y = yy - 2, x = xx - 2;
            float v = 0.f;
            if ((unsigned)y < 16u && (unsigned)x < 16u) {
                int co = cc * 8 + ci;
                int base = b * 8192 + co * 64 + (y >> 1) * 8 + (x >> 1);
                int pos = ((y & 1) << 1) | (x & 1);
                v = (g_idx1[base] == pos) ? s1o[base] : 0.f;
            }
            su[ci][yy][xx] = v;
        }
        for (int i = tid; i < 3200; i += 128) {
            int o = i & 15, r = i >> 4;
            int ci = r / 25, k = r - ci * 25;
            sw[r][o] = w0[(cc * 8 + ci) * 1600 + (og * 16 + o) * 25 + (24 - k)];
        }
        __syncthreads();
        #pragma unroll 1
        for (int ci = 0; ci < 8; ci++) {
            #pragma unroll
            for (int ky = 0; ky < 5; ky++) {
                #pragma unroll
                for (int kx = 0; kx < 5; kx++) {
                    int r = ci * 25 + ky * 5 + kx;
                    unsigned long long wv2[4];
                    #pragma unroll
                    for (int q = 0; q < 4; q++)
                        wv2[q] = *(const unsigned long long*)&sw[r][oh * 8 + 2 * q];
                    #pragma unroll
                    for (int dy = 0; dy < 2; dy++)
                        #pragma unroll
                        for (int dx = 0; dx < 2; dx++) {
                            unsigned long long iv2 = pk2(su[ci][2 * wy + dy + ky][2 * wx + dx + kx]);
                            #pragma unroll
                            for (int q = 0; q < 4; q++) fma2(acc2[dy][dx][q], iv2, wv2[q]);
                        }
                }
            }
        }
        __syncthreads();
    }

    #pragma unroll
    for (int q = 0; q < 4; q++) {
        int o = og * 16 + oh * 8 + 2 * q;
        long base = ((long)(z * BB + b) * 64 + o) * 256;
        #pragma unroll
        for (int dy = 0; dy < 2; dy++)
            #pragma unroll
            for (int dx = 0; dx < 2; dx++) {
                float lo, hi;
                upk(acc2[dy][dx][q], lo, hi);
                int p = (2 * wy + dy) * 16 + (2 * wx + dx);
                g_upscr[base + p] = lo;
                g_upscr[base + 256 + p] = hi;
            }
    }
}

// ============================================================================
// K3b: s2_new = rho(p2 + sum of 8 partials)
// ============================================================================
__global__ void k_s2_epi(float* __restrict__ s2n)
{
    const int ZS = BB * 64 * 256;
    int i = blockIdx.x * 256 + threadIdx.x;
    float s01 = g_upscr[i] + g_upscr[ZS + i];
    float s23 = g_upscr[2 * ZS + i] + g_upscr[3 * ZS + i];
    float s45 = g_upscr[4 * ZS + i] + g_upscr[5 * ZS + i];
    float s67 = g_upscr[6 * ZS + i] + g_upscr[7 * ZS + i];
    s2n[i] = rho(g_p2[i] + ((s01 + s23) + (s45 + s67)));
}

// ============================================================================
extern "C" void kernel_launch(void* const* d_in, const int* in_sizes, int n_in,
                              void* d_out, int out_size)
{
    const float* data = (const float*)d_in[0];
    const float* s0i  = (const float*)d_in[1];
    const float* s1i  = (const float*)d_in[2];
    const float* s2i  = (const float*)d_in[3];
    const float* w0   = (const float*)d_in[4];
    const float* b0   = (const float*)d_in[5];
    const float* w1   = (const float*)d_in[6];
    const float* b1   = (const float*)d_in[7];
    const float* fcw  = (const float*)d_in[8];
    const float* fcb  = (const float*)d_in[9];
    float* out = (float*)d_out;

    float *ps0, *ps1, *ps2;
    cudaGetSymbolAddress((void**)&ps0, g_s0);
    cudaGetSymbolAddress((void**)&ps1, g_s1);
    cudaGetSymbolAddress((void**)&ps2, g_s2);

    // side stream + fork/join events, created once on the first (non-capture)
    // call; every call issues the identical launch sequence.
    static cudaStream_t s_fc = 0;
    static cudaEvent_t evF = 0, evJ = 0;
    if (!s_fc) {
        cudaStreamCreateWithFlags(&s_fc, cudaStreamNonBlocking);
        cudaEventCreateWithFlags(&evF, cudaEventDisableTiming);
        cudaEventCreateWithFlags(&evJ, cudaEventDisableTiming);
    }

    k_p2<<<dim3(64, 4), 256>>>(data, w1, b1);

    const float *cs0 = s0i, *cs1 = s1i, *cs2 = s2i;
    for (int t = 0; t < 10; t++) {
        int nb = t & 1;
        float* ns0 = ps0 + nb * (BB * 10);
        float* ns1 = ps1 + nb * (BB * 8192);
        float* ns2 = ps2 + nb * (BB * 16384);

        // fork: fc chain on side stream (independent of conv chain)
        cudaEventRecord(evF, 0);
        cudaStreamWaitEvent(s_fc, evF, 0);
        k_fc_part<<<dim3(64, 8), 128, 0, s_fc>>>(cs1, fcw);
        k_fc_fin<<<64, 32, 0, s_fc>>>(fcb, ns0);
        cudaEventRecord(evJ, s_fc);

        // main critical path
        k_conv0_half<<<dim3(64, 8, 4), 128>>>(cs2, w0);
        k_pool_epi<<<2048, 256>>>(cs0, b0, fcw, ns1);
        k_upconv_half<<<dim3(64, 4, 8), 128>>>(cs1, w0);
        k_s2_epi<<<4096, 256>>>(ns2);

        // join before anything reads ns0 (next step / output copies)
        cudaStreamWaitEvent(0, evJ, 0);

        cs0 = ns0; cs1 = ns1; cs2 = ns2;
        if (t == 6) {
            cudaMemcpyAsync(out + 1573504, cs0, 640 * sizeof(float),     cudaMemcpyDeviceToDevice, 0);
            cudaMemcpyAsync(out + 1574144, cs1, 524288 * sizeof(float),  cudaMemcpyDeviceToDevice, 0);
            cudaMemcpyAsync(out + 2098432, cs2, 1048576 * sizeof(float), cudaMemcpyDeviceToDevice, 0);
        }
    }
    cudaMemcpyAsync(out,          cs0, 640 * sizeof(float),     cudaMemcpyDeviceToDevice, 0);
    cudaMemcpyAsync(out + 640,    cs1, 524288 * sizeof(float),  cudaMemcpyDeviceToDevice, 0);
    cudaMemcpyAsync(out + 524928, cs2, 1048576 * sizeof(float), cudaMemcpyDeviceToDevice, 0);
}